// round 17
// baseline (speedup 1.0000x reference)
#include <cuda_runtime.h>
#include <cstdint>

// Problem constants
#define CIN     256
#define COUT    256
#define KTOT    2304
#define MTOT    32768
#define NCHK    64        // K chunks
#define CK      36        // real k per chunk (4 ch * 9 taps)
#define CKP     40        // padded to 5 * k8

// Fused-kernel tile geometry: 16(w) x 8(h) pixels per CTA
#define HROWS2  20
#define HCOLS2  28
#define HP2     29
#define NPOS2   (HROWS2 * HP2)   // 580
#define HALO_F  (NPOS2 * 4)      // 2320 floats per halo buffer
#define NSTG2   5

#define APITCH2 44
#define A_SZ2   (COUT * APITCH2)   // 11264 floats
#define B_P     136
#define B_SZ2   (CKP * B_P)        // 5440 floats
#define SMEM_FUSED ((3 * A_SZ2 + 2 * B_SZ2 + 2 * HALO_F) * 4)   // 197248 B

// padded tf32 weights: [cout][chunk][40] (cols 36-39 zero)
__device__ float g_wr2[(size_t)COUT * NCHK * CKP];

// ============================ helpers ============================
__device__ __forceinline__ uint32_t smem_u32(const void* p) {
    uint32_t a;
    asm("{ .reg .u64 t; cvta.to.shared.u64 t, %1; cvt.u32.u64 %0, t; }"
        : "=r"(a) : "l"(p));
    return a;
}
__device__ __forceinline__ uint32_t tf32_rna(float v) {
    uint32_t r;
    asm("cvt.rna.tf32.f32 %0, %1;" : "=r"(r) : "f"(v));
    return r;
}
__device__ __forceinline__ void cp_async16(uint32_t dst, const void* src) {
    asm volatile("cp.async.cg.shared.global [%0], [%1], 16;"
                 :: "r"(dst), "l"(src) : "memory");
}
#define CP_COMMIT()  asm volatile("cp.async.commit_group;" ::: "memory")
#define CP_WAIT(n)   asm volatile("cp.async.wait_group %0;" :: "n"(n) : "memory")

__device__ __forceinline__ void ldsm_x4(uint32_t& r0, uint32_t& r1,
                                        uint32_t& r2, uint32_t& r3, uint32_t addr) {
    asm volatile("ldmatrix.sync.aligned.m8n8.x4.shared.b16 {%0,%1,%2,%3}, [%4];"
                 : "=r"(r0), "=r"(r1), "=r"(r2), "=r"(r3) : "r"(addr));
}
__device__ __forceinline__ void mma_tf32(float* c, const uint32_t* a, const uint32_t* b) {
    asm volatile(
        "mma.sync.aligned.m16n8k8.row.col.f32.tf32.tf32.f32 "
        "{%0,%1,%2,%3}, {%4,%5,%6,%7}, {%8,%9}, {%0,%1,%2,%3};"
        : "+f"(c[0]), "+f"(c[1]), "+f"(c[2]), "+f"(c[3])
        : "r"(a[0]), "r"(a[1]), "r"(a[2]), "r"(a[3]), "r"(b[0]), "r"(b[1]));
}

// ---------------- Kernel 0: round + pad weights ----------------
__global__ __launch_bounds__(256) void round_w2(const float* __restrict__ wt) {
    int i = blockIdx.x * 256 + threadIdx.x;     // < 655360
    int kk   = i % CKP;
    int rest = i / CKP;                         // cout*64 + chunk
    float v = 0.f;
    if (kk < CK)
        v = __uint_as_float(tf32_rna(wt[rest * CK + kk]));
    g_wr2[i] = v;
}

// ---------------- Fused kernel: sample + TF32 GEMM ----------------
// CTA: 256 couts x 128 pixels (16x8 tile). 512 threads, warps 4(M) x 4(N),
// warp tile 64 cout x 32 pix, 5 k8-steps per 40-k chunk.
__global__ __launch_bounds__(512, 1) void fused_kernel(
    const float* __restrict__ x,
    const float* __restrict__ obb,
    const unsigned* __restrict__ stride_ptr,
    float* __restrict__ out)
{
    extern __shared__ __align__(16) float sm[];
    float* As = sm;                               // [3][A_SZ2]
    float* Bs = sm + 3 * A_SZ2;                   // [2][B_SZ2]
    float* Hs = sm + 3 * A_SZ2 + 2 * B_SZ2;       // [2][HALO_F]

    const int tid  = threadIdx.x;
    const int lane = tid & 31;
    const int wid  = tid >> 5;
    const int lq   = lane >> 2;
    const int lt   = lane & 3;
    const int warp_m = (wid & 3) << 6;    // cout base of warp
    const int warp_n = (wid >> 2) << 5;   // pixel base of warp

    const int tileI = blockIdx.x;
    const int n  = tileI >> 7;
    const int t  = tileI & 127;
    const int h0 = (t >> 3) << 3;         // 16 tiles vertically, 8 rows each
    const int w0 = (t & 7) << 4;          // 8 tiles horizontally, 16 cols each

    unsigned su = *stride_ptr;
    float s = (su < 0x00800000u) ? (float)su : __uint_as_float(su);

    // ---- per-thread sampling metadata: pixel p = tid&127, taps by group ----
    const int p  = tid & 127;
    const int tg = tid >> 7;
    const int ntap = (tg == 0) ? 3 : 2;
    const int tap0 = (tg == 0) ? 0 : (2 * tg + 1);
    int    ridx[3];
    float4 rw[3];
    {
        const int ph = p >> 4;
        const int pw = p & 15;
        const int h  = h0 + ph;
        const int w  = w0 + pw;
        const float* ob = obb + (size_t)n * 5 * 16384 + h * 128 + w;
        float xc = ob[0]         / s;
        float yc = ob[16384]     / s;
        float bw = ob[2 * 16384] / s;
        float bh = ob[3 * 16384] / s;
        float th = ob[4 * 16384];
        float sn, cs;
        __sincosf(th, &sn, &cs);
        #pragma unroll
        for (int k = 0; k < 3; k++) {
            int tap = tap0 + k;
            if (k < ntap) {
                float kx = (float)(tap % 3 - 1);
                float ky = (float)(tap / 3 - 1);
                float px = bw * (1.0f / 3.0f) * kx;
                float py = bh * (1.0f / 3.0f) * ky;
                float xa = cs * px - sn * py + xc;
                float ya = sn * px + cs * py + yc;
                float fx = floorf(xa), fy = floorf(ya);
                float lx = xa - fx,    ly = ya - fy;
                int r   = (int)fy - (h0 - 6);
                int col = (int)fx - (w0 - 6);
                r   = min(max(r, 0), HROWS2 - 2);
                col = min(max(col, 0), HCOLS2 - 2);
                ridx[k] = r * HP2 + col;
                rw[k] = make_float4((1.f - ly) * (1.f - lx),
                                    (1.f - ly) * lx,
                                    ly * (1.f - lx),
                                    ly * lx);
            } else { ridx[k] = 0; rw[k] = make_float4(0, 0, 0, 0); }
        }
    }

    const float* xn = x + (size_t)n * CIN * 16384;
    float rv[NSTG2];

    // halo descriptor (recomputed, not stored): returns packed fields
    auto desc_of = [&](int tt, int& dst, int& ch, int& off, bool& valid, bool& act) {
        int i = tid + tt * 512;
        act = (i < HALO_F);
        ch = i / NPOS2;
        int pos = i - ch * NPOS2;
        int rr  = pos / HP2;
        int col = pos - rr * HP2;
        int gy = h0 - 6 + rr;
        int gx = w0 - 6 + col;
        valid = act && (col < HCOLS2) && ((unsigned)gy < 128u) && ((unsigned)gx < 128u);
        off = min(max(gy, 0), 127) * 128 + min(max(gx, 0), 127);
        dst = pos * 4 + ch;
    };
    auto ldgh = [&](int chunk) {
        int cb = chunk * 4;
        #pragma unroll
        for (int tt = 0; tt < NSTG2; tt++) {
            int dst, ch, off; bool valid, act;
            desc_of(tt, dst, ch, off, valid, act);
            rv[tt] = 0.f;
            if (valid)
                rv[tt] = __ldg(xn + (size_t)(cb + ch) * 16384 + off);
        }
    };
    auto scatter = [&](int buf) {
        float* hb = Hs + buf * HALO_F;
        #pragma unroll
        for (int tt = 0; tt < NSTG2; tt++) {
            int dst, ch, off; bool valid, act;
            desc_of(tt, dst, ch, off, valid, act);
            if (act) hb[dst] = rv[tt];
        }
    };
    auto sample = [&](int chunk) {
        const float4* tb = (const float4*)(Hs + (chunk & 1) * HALO_F);
        float* Bb = Bs + (chunk & 1) * B_SZ2;
        #pragma unroll
        for (int k = 0; k < 3; k++) {
            if (k < ntap) {
                int ii = ridx[k];
                float4 wv = rw[k];
                float4 c00 = tb[ii];
                float4 c01 = tb[ii + 1];
                float4 c10 = tb[ii + HP2];
                float4 c11 = tb[ii + HP2 + 1];
                int tap = tap0 + k;
                float v0 = wv.x * c00.x + wv.y * c01.x + wv.z * c10.x + wv.w * c11.x;
                float v1 = wv.x * c00.y + wv.y * c01.y + wv.z * c10.y + wv.w * c11.y;
                float v2 = wv.x * c00.z + wv.y * c01.z + wv.z * c10.z + wv.w * c11.z;
                float v3 = wv.x * c00.w + wv.y * c01.w + wv.z * c10.w + wv.w * c11.w;
                Bb[(0 * 9 + tap) * B_P + p] = __uint_as_float(tf32_rna(v0));
                Bb[(1 * 9 + tap) * B_P + p] = __uint_as_float(tf32_rna(v1));
                Bb[(2 * 9 + tap) * B_P + p] = __uint_as_float(tf32_rna(v2));
                Bb[(3 * 9 + tap) * B_P + p] = __uint_as_float(tf32_rna(v3));
            }
        }
    };
    auto cpa = [&](int chunk, int buf) {
        const float* Aw = g_wr2 + (size_t)chunk * CKP;
        uint32_t base = smem_u32(As + buf * A_SZ2);
        #pragma unroll
        for (int i = 0; i < 5; i++) {
            int id = tid + i * 512;          // 0..2559
            int r  = id / 10;
            int q  = id - r * 10;
            cp_async16(base + (uint32_t)(r * APITCH2 + q * 4) * 4,
                       Aw + (size_t)r * (NCHK * CKP) + q * 4);
        }
        CP_COMMIT();
    };

    float acc[4][4][4];
    #pragma unroll
    for (int i = 0; i < 4; i++)
        #pragma unroll
        for (int j = 0; j < 4; j++)
            #pragma unroll
            for (int r = 0; r < 4; r++)
                acc[i][j][r] = 0.f;

    // zero B buffers (pad rows must be 0)
    for (int i = tid; i < 2 * B_SZ2; i += 512)
        Bs[i] = 0.f;

    // ---- prologue ----
    ldgh(0);
    scatter(0);
    ldgh(1);
    cpa(0, 0);
    cpa(1, 1);
    __syncthreads();           // halo0 + B zeros visible
    sample(0);                 // chunk0 -> B[0]
    scatter(1);                // halo1
    ldgh(2);                   // rv = halo2

    const uint32_t a_row = (uint32_t)(warp_m + (lane & 15));
    const uint32_t a_ko  = ((lane >> 4) & 1) << 2;

    // ---- main loop ----
    for (int c = 0; c < NCHK; c++) {
        if (c < NCHK - 1) { CP_WAIT(1); } else { CP_WAIT(0); }
        __syncthreads();   // A_c visible; B_c sampled; halo_{c+1} scattered

        if (c + 2 < NCHK) scatter(c & 1);          // halo c+2 -> Hs[c&1]
        if (c + 1 < NCHK) sample(c + 1);           // -> B[(c+1)&1]
        if (c + 3 < NCHK) ldgh(c + 3);
        if (c + 2 < NCHK) cpa(c + 2, (c + 2) % 3);

        // mma chunk c
        const uint32_t ab = smem_u32(As + (c % 3) * A_SZ2);
        const float* Bb = Bs + (c & 1) * B_SZ2;
        #pragma unroll
        for (int sstep = 0; sstep < 5; sstep++) {
            const uint32_t ks = (uint32_t)(sstep << 3);
            const float* bp0 = Bb + (ks + lt) * B_P + warp_n + lq;
            uint32_t b[4][2];
            #pragma unroll
            for (int bn = 0; bn < 4; bn++) {
                b[bn][0] = __float_as_uint(bp0[bn << 3]);
                b[bn][1] = __float_as_uint(bp0[4 * B_P + (bn << 3)]);
            }
            #pragma unroll
            for (int am = 0; am < 4; am++) {
                uint32_t a[4];
                uint32_t addr = ab + (uint32_t)((a_row + (am << 4)) * APITCH2 + ks + a_ko) * 4;
                ldsm_x4(a[0], a[1], a[2], a[3], addr);
                #pragma unroll
                for (int bn = 0; bn < 4; bn++)
                    mma_tf32(acc[am][bn], a, b[bn]);
            }
        }
    }

    // ---- epilogue: out[img][cout][hw] ----
    #pragma unroll
    for (int am = 0; am < 4; am++) {
        #pragma unroll
        for (int bn = 0; bn < 4; bn++) {
            int cout = warp_m + (am << 4) + lq;
            int pl   = warp_n + (bn << 3) + (lt << 1);      // local pixel
            int hw   = (h0 + (pl >> 4)) * 128 + w0 + (pl & 15);
            float* p0 = out + ((size_t)n << 22) + ((size_t)cout << 14) + hw;
            *(float2*)p0 = make_float2(acc[am][bn][0], acc[am][bn][1]);
            *(float2*)(p0 + ((size_t)8 << 14)) =
                make_float2(acc[am][bn][2], acc[am][bn][3]);
        }
    }
}

extern "C" void kernel_launch(void* const* d_in, const int* in_sizes, int n_in,
                              void* d_out, int out_size) {
    const float*    x   = (const float*)d_in[0];
    const float*    obb = (const float*)d_in[1];
    const float*    wt  = (const float*)d_in[2];
    const unsigned* st  = (const unsigned*)d_in[3];
    float* out = (float*)d_out;

    cudaFuncSetAttribute(fused_kernel, cudaFuncAttributeMaxDynamicSharedMemorySize,
                         SMEM_FUSED);

    round_w2<<<(COUT * NCHK * CKP) / 256, 256>>>(wt);
    fused_kernel<<<256, 512, SMEM_FUSED>>>(x, obb, st, out);
}